// round 4
// baseline (speedup 1.0000x reference)
#include <cuda_runtime.h>
#include <cstdint>
#include <cstddef>

#define NB    4
#define NSRC  16384
#define NTGT  4096
#define KNN   32
#define FULLM 0xffffffffu

// spatial grid
#define G     32
#define NCELL (G*G*G)
#define LB    6.0f
#define GH    0.375f          // 2*LB/G
#define INVH  (1.0f/GH)

// Output layout (flattened concat, all float32):
#define OFF_PATCH 0
#define OFF_IDX   1572864
#define OFF_SIZE  2621440
#define OFF_RAD   2637824
#define OFF_DIST  2637828

// __device__ scratch (no allocations allowed)
__device__ int    g_cnt[NB * NCELL];
__device__ int    g_cur[NB * NCELL];
__device__ int    g_start[NB * (NCELL + 1)];
__device__ float4 g_pts[NB * NSRC];   // sorted-by-cell packed (x,y,z,sumsq)
__device__ int    g_pidx[NB * NSRC];  // original within-batch index

__device__ __forceinline__ int cellcoord(float v) {
    int c = (int)floorf((v + LB) * INVH);
    return min(G - 1, max(0, c));
}

__global__ void k_zero() {
    int i = blockIdx.x * blockDim.x + threadIdx.x;
    if (i < NB * NCELL) g_cnt[i] = 0;
}

__global__ void k_count(const float* __restrict__ src) {
    int i = blockIdx.x * blockDim.x + threadIdx.x;
    if (i >= NB * NSRC) return;
    int b = i / NSRC;
    float x = src[3 * i], y = src[3 * i + 1], z = src[3 * i + 2];
    int cell = (cellcoord(z) * G + cellcoord(y)) * G + cellcoord(x);
    atomicAdd(&g_cnt[b * NCELL + cell], 1);
}

#define CPT (NCELL / 1024)
__global__ void k_scan() {
    __shared__ int sm[1024];
    int b = blockIdx.x, t = threadIdx.x;
    const int* cnt = g_cnt + b * NCELL;
    int* start = g_start + b * (NCELL + 1);
    int* cur   = g_cur + b * NCELL;
    int s = 0;
    #pragma unroll
    for (int c = 0; c < CPT; c++) s += cnt[t * CPT + c];
    sm[t] = s; __syncthreads();
    for (int off = 1; off < 1024; off <<= 1) {
        int v = (t >= off) ? sm[t - off] : 0;
        __syncthreads();
        sm[t] += v;
        __syncthreads();
    }
    int run = sm[t] - s;   // exclusive prefix of this thread's chunk
    #pragma unroll
    for (int c = 0; c < CPT; c++) {
        int id = t * CPT + c;
        start[id] = run; cur[id] = run;
        run += cnt[id];
    }
    if (t == 1023) start[NCELL] = NSRC;
}

__global__ void k_scatter(const float* __restrict__ src) {
    int i = blockIdx.x * blockDim.x + threadIdx.x;
    if (i >= NB * NSRC) return;
    int b = i / NSRC;
    float x = src[3 * i], y = src[3 * i + 1], z = src[3 * i + 2];
    int cell = (cellcoord(z) * G + cellcoord(y)) * G + cellcoord(x);
    int pos = atomicAdd(&g_cur[b * NCELL + cell], 1);
    float ss = __fadd_rn(__fadd_rn(__fmul_rn(x, x), __fmul_rn(y, y)), __fmul_rn(z, z));
    g_pts[b * NSRC + pos]  = make_float4(x, y, z, ss);
    g_pidx[b * NSRC + pos] = i - b * NSRC;
}

// One warp per target. Expanding Chebyshev-shell search over the grid.
// Top-K kept warp-sorted ascending under lexicographic (value, index) order,
// which equals jax top_k semantics (ties -> lower index) under ANY scan order.
__global__ __launch_bounds__(256) void k_query(const float* __restrict__ src,
                                               const float* __restrict__ tgt,
                                               float* __restrict__ out) {
    const int warp = threadIdx.x >> 5;
    const int lane = threadIdx.x & 31;
    const int tg   = blockIdx.x * 8 + warp;     // 0..16383
    const int b    = tg / NTGT;

    const float px = tgt[3 * tg], py = tgt[3 * tg + 1], pz = tgt[3 * tg + 2];
    const float tt = __fadd_rn(__fadd_rn(__fmul_rn(px, px), __fmul_rn(py, py)),
                               __fmul_rn(pz, pz));

    const int cx = cellcoord(px), cy = cellcoord(py), cz = cellcoord(pz);
    // overflow distance beyond clamped cell box (nonzero only for clamped targets)
    float ex = fmaxf(fmaxf(-LB - px, px - LB), 0.0f);
    float ey = fmaxf(fmaxf(-LB - py, py - LB), 0.0f);
    float ez = fmaxf(fmaxf(-LB - pz, pz - LB), 0.0f);
    const float e = sqrtf(ex * ex + ey * ey + ez * ez);

    const float INF = __int_as_float(0x7f800000);
    float lv = INF; int li = 0x7fffffff;        // lane = rank in sorted list
    float thr_v = INF; int thr_i = 0x7fffffff;  // lane-31 entry, replicated

    const int*    cstart = g_start + b * (NCELL + 1);
    const float4* pts    = g_pts + b * NSRC;
    const int*    pidx   = g_pidx + b * NSRC;

    const int dmax = max(max(max(cx, G - 1 - cx), max(cy, G - 1 - cy)),
                         max(cz, G - 1 - cz));

    // process candidates in cells row [zc][yc][x0..x1] (x-contiguous in memory)
    auto process = [&](int zc, int yc, int x0, int x1) {
        const int cbase = (zc * G + yc) * G;
        const int p0 = cstart[cbase + x0];
        const int p1 = cstart[cbase + x1 + 1];
        for (int base = p0; base < p1; base += 32) {
            const int ii = base + lane;
            float sqv = INF; int jj = 0x7fffffff;
            if (ii < p1) {
                const float4 S = pts[ii];
                jj = pidx[ii];
                float dot = __fmaf_rn(pz, S.z, __fmaf_rn(py, S.y, __fmul_rn(px, S.x)));
                sqv = __fadd_rn(__fsub_rn(tt, __fmul_rn(2.0f, dot)), S.w);
            }
            const bool acc = (sqv < thr_v) || (sqv == thr_v && jj < thr_i);
            unsigned ball = __ballot_sync(FULLM, acc);
            while (ball) {
                const int   sl = __ffs(ball) - 1;
                ball &= ball - 1;
                const float nv = __shfl_sync(FULLM, sqv, sl);
                const int   nj = __shfl_sync(FULLM, jj,  sl);
                const unsigned le = __ballot_sync(FULLM, (lv < nv) || (lv == nv && li < nj));
                const int pos = __popc(le);
                if (pos < 32) {                 // stale candidates drop out here
                    const float pv = __shfl_up_sync(FULLM, lv, 1);
                    const int   pj = __shfl_up_sync(FULLM, li, 1);
                    if (lane > pos)       { lv = pv; li = pj; }
                    else if (lane == pos) { lv = nv; li = nj; }
                }
            }
            thr_v = __shfl_sync(FULLM, lv, 31);
            thr_i = __shfl_sync(FULLM, li, 31);
        }
    };

    for (int d = 0;; ++d) {
        if (d == 0) {
            process(cz, cy, cx, cx);
        } else {
            for (int zo = -d; zo <= d; ++zo) {
                const int zc = cz + zo;
                if (zc < 0 || zc >= G) continue;
                const int az = zo < 0 ? -zo : zo;
                for (int yo = -d; yo <= d; ++yo) {
                    const int yc = cy + yo;
                    if (yc < 0 || yc >= G) continue;
                    const int ay = yo < 0 ? -yo : yo;
                    if (az == d || ay == d) {
                        const int x0 = max(cx - d, 0);
                        const int x1 = min(cx + d, G - 1);
                        process(zc, yc, x0, x1);
                    } else {
                        if (cx - d >= 0)    process(zc, yc, cx - d, cx - d);
                        if (cx + d <= G - 1) process(zc, yc, cx + d, cx + d);
                    }
                }
            }
        }
        const float dm = __fmaf_rn((float)d, GH, -e);
        if (dm > 0.0f && thr_v < dm * dm) break;  // strict: protects index ties
        if (d >= dmax) break;                     // whole grid covered
    }

    // ---- outputs ----
    const float rad  = 0.2f;
    const float rad2 = __fmul_rn(rad, rad);
    const bool  mask = (rad2 >= lv);

    float gx = 0.0f, gy = 0.0f, gz = 0.0f;
    if (mask) {
        const float* sp = src + (size_t)(b * NSRC + li) * 3;
        gx = __fdiv_rn(sp[0], rad);
        gy = __fdiv_rn(sp[1], rad);
        gz = __fdiv_rn(sp[2], rad);
    }
    const float tdx = __fdiv_rn(px, rad);
    const float tdy = __fdiv_rn(py, rad);
    const float tdz = __fdiv_rn(pz, rad);

    const size_t ee = (size_t)tg * KNN + lane;

    float* patches = out + OFF_PATCH;
    patches[3 * ee + 0] = __fsub_rn(gx, tdx);
    patches[3 * ee + 1] = __fsub_rn(gy, tdy);
    patches[3 * ee + 2] = __fsub_rn(gz, tdz);

    float* idxf = out + OFF_IDX;
    idxf[2 * ee + 0] = (float)b;
    idxf[2 * ee + 1] = (float)(mask ? li : -1);

    float* pdist = out + OFF_DIST;
    pdist[ee] = __fdiv_rn(__fsqrt_rn(fmaxf(lv, 1e-9f)), rad);

    const unsigned mball = __ballot_sync(FULLM, mask);
    if (lane == 0) {
        float* psize = out + OFF_SIZE;
        psize[tg] = (float)__popc(mball);
    }

    if (blockIdx.x == 0 && threadIdx.x < NB) {
        float* prad = out + OFF_RAD;
        prad[threadIdx.x] = rad;
    }
}

extern "C" void kernel_launch(void* const* d_in, const int* in_sizes, int n_in,
                              void* d_out, int out_size) {
    const float* src = (const float*)d_in[0];
    const float* tgt = (const float*)d_in[1];
    if (n_in >= 2 && in_sizes[0] == NB * NTGT * 3 && in_sizes[1] == NB * NSRC * 3) {
        src = (const float*)d_in[1];
        tgt = (const float*)d_in[0];
    }
    float* out = (float*)d_out;

    k_zero   <<<(NB * NCELL + 255) / 256, 256>>>();
    k_count  <<<(NB * NSRC + 255) / 256, 256>>>(src);
    k_scan   <<<NB, 1024>>>();
    k_scatter<<<(NB * NSRC + 255) / 256, 256>>>(src);
    k_query  <<<(NB * NTGT) / 8, 256>>>(src, tgt, out);
}

// round 5
// speedup vs baseline: 1.6553x; 1.6553x over previous
#include <cuda_runtime.h>
#include <cstdint>
#include <cstddef>

#define NB    4
#define NSRC  16384
#define NTGT  4096
#define KNN   32
#define FULLM 0xffffffffu

// spatial grid
#define G     32
#define NCELL (G*G*G)
#define LB    6.0f
#define GH    0.375f
#define INVH  (1.0f/GH)

// Output layout (flattened concat, all float32):
#define OFF_PATCH 0
#define OFF_IDX   1572864
#define OFF_SIZE  2621440
#define OFF_RAD   2637824
#define OFF_DIST  2637828

__device__ int    g_cnt[NB * NCELL];
__device__ int    g_cur[NB * NCELL];
__device__ int    g_start[NB * (NCELL + 1)];
__device__ float4 g_pts[NB * NSRC];
__device__ int    g_pidx[NB * NSRC];

__device__ __forceinline__ int cellcoord(float v) {
    int c = (int)floorf((v + LB) * INVH);
    return min(G - 1, max(0, c));
}

__global__ void k_zero() {
    int i = blockIdx.x * blockDim.x + threadIdx.x;
    if (i < NB * NCELL) g_cnt[i] = 0;
}

__global__ void k_count(const float* __restrict__ src) {
    int i = blockIdx.x * blockDim.x + threadIdx.x;
    if (i >= NB * NSRC) return;
    int b = i / NSRC;
    float x = src[3 * i], y = src[3 * i + 1], z = src[3 * i + 2];
    int cell = (cellcoord(z) * G + cellcoord(y)) * G + cellcoord(x);
    atomicAdd(&g_cnt[b * NCELL + cell], 1);
}

#define CPT (NCELL / 1024)
__global__ void k_scan() {
    __shared__ int sm[1024];
    int b = blockIdx.x, t = threadIdx.x;
    const int* cnt = g_cnt + b * NCELL;
    int* start = g_start + b * (NCELL + 1);
    int* cur   = g_cur + b * NCELL;
    int s = 0;
    #pragma unroll
    for (int c = 0; c < CPT; c++) s += cnt[t * CPT + c];
    sm[t] = s; __syncthreads();
    for (int off = 1; off < 1024; off <<= 1) {
        int v = (t >= off) ? sm[t - off] : 0;
        __syncthreads();
        sm[t] += v;
        __syncthreads();
    }
    int run = sm[t] - s;
    #pragma unroll
    for (int c = 0; c < CPT; c++) {
        int id = t * CPT + c;
        start[id] = run; cur[id] = run;
        run += cnt[id];
    }
    if (t == 1023) start[NCELL] = NSRC;
}

__global__ void k_scatter(const float* __restrict__ src) {
    int i = blockIdx.x * blockDim.x + threadIdx.x;
    if (i >= NB * NSRC) return;
    int b = i / NSRC;
    float x = src[3 * i], y = src[3 * i + 1], z = src[3 * i + 2];
    int cell = (cellcoord(z) * G + cellcoord(y)) * G + cellcoord(x);
    int pos = atomicAdd(&g_cur[b * NCELL + cell], 1);
    float ss = __fadd_rn(__fadd_rn(__fmul_rn(x, x), __fmul_rn(y, y)), __fmul_rn(z, z));
    g_pts[b * NSRC + pos]  = make_float4(x, y, z, ss);
    g_pidx[b * NSRC + pos] = i - b * NSRC;
}

// One warp per target. Exact KNN via expanding Chebyshev shells with:
//  - lane-parallel segment (cell-row) range prefetch + warp scan
//  - flat candidate stream (binary search over smem segment prefix)
//  - bitonic initial fill, then lex (value,index) sorted-insertion
__global__ __launch_bounds__(256) void k_query(const float* __restrict__ src,
                                               const float* __restrict__ tgt,
                                               float* __restrict__ out) {
    __shared__ int s_p0 [8][32];
    __shared__ int s_pre[8][32];

    const int w    = threadIdx.x >> 5;
    const int lane = threadIdx.x & 31;
    const int tg   = blockIdx.x * 8 + w;
    const int b    = tg / NTGT;

    const float px = tgt[3 * tg], py = tgt[3 * tg + 1], pz = tgt[3 * tg + 2];
    const float tt = __fadd_rn(__fadd_rn(__fmul_rn(px, px), __fmul_rn(py, py)),
                               __fmul_rn(pz, pz));

    const int cx = cellcoord(px), cy = cellcoord(py), cz = cellcoord(pz);
    float ex = fmaxf(fmaxf(-LB - px, px - LB), 0.0f);
    float ey = fmaxf(fmaxf(-LB - py, py - LB), 0.0f);
    float ez = fmaxf(fmaxf(-LB - pz, pz - LB), 0.0f);
    const float e = sqrtf(ex * ex + ey * ey + ez * ez);

    const float INF = __int_as_float(0x7f800000);
    const int   IMAX = 0x7fffffff;
    float lv = INF; int li = IMAX;
    float thr_v = INF; int thr_i = IMAX;
    bool filled = false;

    const int*    cstart = g_start + b * (NCELL + 1);
    const float4* pts    = g_pts + b * NSRC;
    const int*    pidx   = g_pidx + b * NSRC;

    const int dmax = max(max(max(cx, G - 1 - cx), max(cy, G - 1 - cy)),
                         max(cz, G - 1 - cz));

    for (int d = 0;; ++d) {
        const int nseg = (d == 0) ? 1 : (8 * d + 2 * (2 * d - 1) * (2 * d - 1));
        for (int bk = 0; bk < nseg; bk += 32) {
            // ---- lane-parallel segment ranges ----
            const int k = bk + lane;
            bool valid = (k < nseg);
            int zc = cz, yc = cy, x0 = cx, x1 = cx;
            if (valid && d > 0) {
                if (k < 8 * d) {                 // perimeter rows (full x span)
                    const int side = k / (2 * d), off = k % (2 * d);
                    int zo, yo;
                    if      (side == 0) { zo = -d;       yo = -d + off; }
                    else if (side == 1) { yo =  d;       zo = -d + off; }
                    else if (side == 2) { zo =  d;       yo =  d - off; }
                    else                { yo = -d;       zo =  d - off; }
                    zc = cz + zo; yc = cy + yo;
                    x0 = max(cx - d, 0); x1 = min(cx + d, G - 1);
                } else {                          // inner rows: 2 single cells
                    const int k2 = k - 8 * d;
                    const int w2 = 2 * d - 1;
                    const int r = k2 >> 1, side = k2 & 1;
                    zc = cz + (-d + 1 + r / w2);
                    yc = cy + (-d + 1 + r % w2);
                    const int x = side ? (cx + d) : (cx - d);
                    x0 = x1 = x;
                    if (x < 0 || x >= G) valid = false;
                }
                if (zc < 0 || zc >= G || yc < 0 || yc >= G) valid = false;
            }
            int p0 = 0, len = 0;
            if (valid) {
                const int cb = (zc * G + yc) * G;
                p0  = cstart[cb + x0];
                len = cstart[cb + x1 + 1] - p0;
            }
            // exclusive warp scan of len
            int pre = len;
            #pragma unroll
            for (int off = 1; off < 32; off <<= 1) {
                int n = __shfl_up_sync(FULLM, pre, off);
                if (lane >= off) pre += n;
            }
            const int total = __shfl_sync(FULLM, pre, 31);
            pre -= len;
            s_p0 [w][lane] = p0;
            s_pre[w][lane] = pre;
            __syncwarp(FULLM);
            if (total == 0) continue;

            // ---- flat candidate stream ----
            for (int base = 0; base < total; base += 32) {
                const int pos = base + lane;
                float sqv = INF; int jj = IMAX;
                if (pos < total) {
                    int lo = 0;              // max s with pre[s] <= pos
                    #pragma unroll
                    for (int step = 16; step; step >>= 1) {
                        const int cand = lo + step;
                        if (cand < 32 && s_pre[w][cand] <= pos) lo = cand;
                    }
                    const int ii = s_p0[w][lo] + (pos - s_pre[w][lo]);
                    const float4 S = pts[ii];
                    jj = pidx[ii];
                    float dot = __fmaf_rn(pz, S.z, __fmaf_rn(py, S.y, __fmul_rn(px, S.x)));
                    sqv = __fadd_rn(__fsub_rn(tt, __fmul_rn(2.0f, dot)), S.w);
                }
                if (!filled) {
                    // bitonic sort of 32 (value,index) pairs, ascending lex
                    #pragma unroll
                    for (int kk = 2; kk <= 32; kk <<= 1) {
                        #pragma unroll
                        for (int j = kk >> 1; j > 0; j >>= 1) {
                            const float ov = __shfl_xor_sync(FULLM, sqv, j);
                            const int   oi = __shfl_xor_sync(FULLM, jj,  j);
                            const bool dirAsc = ((lane & kk) == 0);
                            const bool otherLess = (ov < sqv) || (ov == sqv && oi < jj);
                            const bool lower = (lane & j) == 0;   // lane < partner
                            const bool keepOther = lower ? (dirAsc ? otherLess : !otherLess)
                                                         : (dirAsc ? !otherLess : otherLess);
                            if (keepOther) { sqv = ov; jj = oi; }
                        }
                    }
                    lv = sqv; li = jj;
                    thr_v = __shfl_sync(FULLM, lv, 31);
                    thr_i = __shfl_sync(FULLM, li, 31);
                    filled = true;
                } else {
                    const bool acc = (sqv < thr_v) || (sqv == thr_v && jj < thr_i);
                    unsigned ball = __ballot_sync(FULLM, acc);
                    if (ball) {
                        do {
                            const int   sl = __ffs(ball) - 1;
                            ball &= ball - 1;
                            const float nv = __shfl_sync(FULLM, sqv, sl);
                            const int   nj = __shfl_sync(FULLM, jj,  sl);
                            const unsigned le =
                                __ballot_sync(FULLM, (lv < nv) || (lv == nv && li < nj));
                            const int ppos = __popc(le);
                            if (ppos < 32) {
                                const float pv = __shfl_up_sync(FULLM, lv, 1);
                                const int   pj = __shfl_up_sync(FULLM, li, 1);
                                if (lane > ppos)       { lv = pv; li = pj; }
                                else if (lane == ppos) { lv = nv; li = nj; }
                            }
                        } while (ball);
                        thr_v = __shfl_sync(FULLM, lv, 31);
                        thr_i = __shfl_sync(FULLM, li, 31);
                    }
                }
            }
        }
        const float dm = __fmaf_rn((float)d, GH, -e);
        if (dm > 0.0f && thr_v < dm * dm) break;
        if (d >= dmax) break;
    }

    // ---- outputs ----
    const float rad  = 0.2f;
    const float rad2 = __fmul_rn(rad, rad);
    const bool  mask = (rad2 >= lv);

    float gx = 0.0f, gy = 0.0f, gz = 0.0f;
    if (mask) {
        const float* sp = src + (size_t)(b * NSRC + li) * 3;
        gx = __fdiv_rn(sp[0], rad);
        gy = __fdiv_rn(sp[1], rad);
        gz = __fdiv_rn(sp[2], rad);
    }
    const float tdx = __fdiv_rn(px, rad);
    const float tdy = __fdiv_rn(py, rad);
    const float tdz = __fdiv_rn(pz, rad);

    const size_t ee = (size_t)tg * KNN + lane;

    float* patches = out + OFF_PATCH;
    patches[3 * ee + 0] = __fsub_rn(gx, tdx);
    patches[3 * ee + 1] = __fsub_rn(gy, tdy);
    patches[3 * ee + 2] = __fsub_rn(gz, tdz);

    float* idxf = out + OFF_IDX;
    idxf[2 * ee + 0] = (float)b;
    idxf[2 * ee + 1] = (float)(mask ? li : -1);

    float* pdist = out + OFF_DIST;
    pdist[ee] = __fdiv_rn(__fsqrt_rn(fmaxf(lv, 1e-9f)), rad);

    const unsigned mball = __ballot_sync(FULLM, mask);
    if (lane == 0) {
        float* psize = out + OFF_SIZE;
        psize[tg] = (float)__popc(mball);
    }

    if (blockIdx.x == 0 && threadIdx.x < NB) {
        float* prad = out + OFF_RAD;
        prad[threadIdx.x] = rad;
    }
}

extern "C" void kernel_launch(void* const* d_in, const int* in_sizes, int n_in,
                              void* d_out, int out_size) {
    const float* src = (const float*)d_in[0];
    const float* tgt = (const float*)d_in[1];
    if (n_in >= 2 && in_sizes[0] == NB * NTGT * 3 && in_sizes[1] == NB * NSRC * 3) {
        src = (const float*)d_in[1];
        tgt = (const float*)d_in[0];
    }
    float* out = (float*)d_out;

    k_zero   <<<(NB * NCELL + 255) / 256, 256>>>();
    k_count  <<<(NB * NSRC + 255) / 256, 256>>>(src);
    k_scan   <<<NB, 1024>>>();
    k_scatter<<<(NB * NSRC + 255) / 256, 256>>>(src);
    k_query  <<<(NB * NTGT) / 8, 256>>>(src, tgt, out);
}